// round 2
// baseline (speedup 1.0000x reference)
#include <cuda_runtime.h>
#include <cuda_bf16.h>

namespace {

constexpr int B  = 2;
constexpr int H  = 16;
constexpr int S  = 2048;
constexpr int D  = 128;
constexpr int HK = 4;
constexpr int I  = 2048;
constexpr int GQ = H / HK;   // 4

constexpr float SCALE = 0.08838834764831843f;  // 128^-0.5

constexpr int BM = 64;       // rows per block
constexpr int BI = 64;       // i-chunk
constexpr int THREADS = 256;
constexpr int PADD = D + 1;  // 129: odd stride -> <=2-way LDS conflicts
constexpr int PADI = BI + 1; // 65

struct SmemLayout {
    float Q[BM][PADD];
    float K[BI][PADD];
    float U[BI][PADD];
    float V[BI][PADD];
    float A[BM][PADI];
};

} // namespace

__global__ __launch_bounds__(THREADS, 1)
void flash_mlp_kernel(const float* __restrict__ gQ,
                      const float* __restrict__ gK,
                      const float* __restrict__ gU,
                      const float* __restrict__ gV,
                      float* __restrict__ gO) {
    extern __shared__ float smem_raw[];
    SmemLayout& sm = *reinterpret_cast<SmemLayout*>(smem_raw);

    const int tid   = threadIdx.x;
    const int tileM = blockIdx.x;       // 0 .. S/BM-1
    const int bh    = blockIdx.y;       // 0 .. B*H-1
    const int h     = bh % H;
    const int hk    = h / GQ;

    const float* qBase = gQ + ((size_t)bh * S + (size_t)tileM * BM) * D;
    const float* kBase = gK + (size_t)hk * I * D;
    const float* uBase = gU + (size_t)hk * I * D;
    const float* vBase = gV + (size_t)hk * I * D;
    float*       oBase = gO + ((size_t)bh * S + (size_t)tileM * BM) * D;

    // ---- load Q tile (64 x 128), float4 global reads, scalar smem writes ----
    #pragma unroll
    for (int it = 0; it < 8; ++it) {
        int idx4 = tid + it * THREADS;        // 0..2047
        int r    = idx4 >> 5;                 // /32
        int c4   = (idx4 & 31) << 2;
        float4 v = *reinterpret_cast<const float4*>(qBase + r * D + c4);
        sm.Q[r][c4 + 0] = v.x;
        sm.Q[r][c4 + 1] = v.y;
        sm.Q[r][c4 + 2] = v.z;
        sm.Q[r][c4 + 3] = v.w;
    }

    float oAcc[4][8];
    #pragma unroll
    for (int x = 0; x < 4; ++x)
        #pragma unroll
        for (int y = 0; y < 8; ++y) oAcc[x][y] = 0.0f;

    const int tr = tid >> 4;   // 0..15
    const int tc = tid & 15;   // 0..15

    for (int chunk = 0; chunk < I / BI; ++chunk) {
        __syncthreads();   // previous phase-3 reads of sm.V done before reload

        // ---- load K, U, V chunks (each 64 x 128) ----
        const float* kC = kBase + (size_t)chunk * BI * D;
        const float* uC = uBase + (size_t)chunk * BI * D;
        const float* vC = vBase + (size_t)chunk * BI * D;
        #pragma unroll
        for (int it = 0; it < 8; ++it) {
            int idx4 = tid + it * THREADS;
            int r    = idx4 >> 5;
            int c4   = (idx4 & 31) << 2;
            float4 a = *reinterpret_cast<const float4*>(kC + r * D + c4);
            sm.K[r][c4 + 0] = a.x; sm.K[r][c4 + 1] = a.y;
            sm.K[r][c4 + 2] = a.z; sm.K[r][c4 + 3] = a.w;
            float4 b = *reinterpret_cast<const float4*>(uC + r * D + c4);
            sm.U[r][c4 + 0] = b.x; sm.U[r][c4 + 1] = b.y;
            sm.U[r][c4 + 2] = b.z; sm.U[r][c4 + 3] = b.w;
            float4 c = *reinterpret_cast<const float4*>(vC + r * D + c4);
            sm.V[r][c4 + 0] = c.x; sm.V[r][c4 + 1] = c.y;
            sm.V[r][c4 + 2] = c.z; sm.V[r][c4 + 3] = c.w;
        }
        __syncthreads();

        // ---- phase 1: M = Q*K^T, N = Q*U^T  (4x4 micro-tiles) ----
        float mAcc[4][4] = {};
        float nAcc[4][4] = {};
        #pragma unroll 4
        for (int k = 0; k < D; ++k) {
            float a[4], bk[4], bu[4];
            #pragma unroll
            for (int x = 0; x < 4; ++x) a[x] = sm.Q[tr * 4 + x][k];
            #pragma unroll
            for (int y = 0; y < 4; ++y) {
                bk[y] = sm.K[tc * 4 + y][k];
                bu[y] = sm.U[tc * 4 + y][k];
            }
            #pragma unroll
            for (int x = 0; x < 4; ++x)
                #pragma unroll
                for (int y = 0; y < 4; ++y) {
                    mAcc[x][y] = fmaf(a[x], bk[y], mAcc[x][y]);
                    nAcc[x][y] = fmaf(a[x], bu[y], nAcc[x][y]);
                }
        }

        // ---- phase 2: A = silu(M*scale) * (N*scale) ----
        #pragma unroll
        for (int x = 0; x < 4; ++x)
            #pragma unroll
            for (int y = 0; y < 4; ++y) {
                float m = mAcc[x][y] * SCALE;
                float n = nAcc[x][y] * SCALE;
                float s = m / (1.0f + __expf(-m));   // silu
                sm.A[tr * 4 + x][tc * 4 + y] = s * n;
            }
        __syncthreads();

        // ---- phase 3: O += A @ V  (4x8 micro-tiles) ----
        #pragma unroll 4
        for (int ii = 0; ii < BI; ++ii) {
            float a[4], v[8];
            #pragma unroll
            for (int x = 0; x < 4; ++x) a[x] = sm.A[tr * 4 + x][ii];
            #pragma unroll
            for (int y = 0; y < 8; ++y) v[y] = sm.V[ii][tc * 8 + y];
            #pragma unroll
            for (int x = 0; x < 4; ++x)
                #pragma unroll
                for (int y = 0; y < 8; ++y)
                    oAcc[x][y] = fmaf(a[x], v[y], oAcc[x][y]);
        }
    }

    // ---- store O tile: rows tr*4+x, cols tc*8 .. tc*8+7, float4 stores ----
    #pragma unroll
    for (int x = 0; x < 4; ++x) {
        float* dst = oBase + (size_t)(tr * 4 + x) * D + tc * 8;
        float4 v0 = make_float4(oAcc[x][0], oAcc[x][1], oAcc[x][2], oAcc[x][3]);
        float4 v1 = make_float4(oAcc[x][4], oAcc[x][5], oAcc[x][6], oAcc[x][7]);
        *reinterpret_cast<float4*>(dst)     = v0;
        *reinterpret_cast<float4*>(dst + 4) = v1;
    }
}

extern "C" void kernel_launch(void* const* d_in, const int* in_sizes, int n_in,
                              void* d_out, int out_size) {
    const float* Q = (const float*)d_in[0];
    const float* K = (const float*)d_in[1];
    const float* U = (const float*)d_in[2];
    const float* V = (const float*)d_in[3];
    float* O = (float*)d_out;

    const int smem = (int)sizeof(SmemLayout);   // ~148.7 KB
    cudaFuncSetAttribute(flash_mlp_kernel,
                         cudaFuncAttributeMaxDynamicSharedMemorySize, smem);

    dim3 grid(S / BM, B * H);   // (32, 32)
    flash_mlp_kernel<<<grid, THREADS, smem>>>(Q, K, U, V, O);
}

// round 4
// speedup vs baseline: 10.3936x; 10.3936x over previous
#include <cuda_runtime.h>
#include <cuda_fp16.h>
#include <cstdint>

#define DEVINL __device__ __forceinline__

namespace {

constexpr int NB = 2, NH = 16, S = 2048, D = 128, HK = 4, NI = 2048;
constexpr float SCALE = 0.08838834764831843f;   // 128^-0.5

constexpr int BM = 128;            // q rows per CTA
constexpr int BI = 64;             // i-chunk
constexpr int NCHUNK = NI / BI;    // 32
constexpr int THREADS = 256;       // 8 warps, all compute

// smem byte offsets
constexpr uint32_t SQ    = 0;                       // 128 rows x 256B = 32768
constexpr uint32_t STG0  = 32768;                   // stage buffers
constexpr uint32_t OFF_K = 0;                       // within stage
constexpr uint32_t OFF_U = 16384;
constexpr uint32_t OFF_V = 32768;
constexpr uint32_t STAGE_BYTES = 49152;             // K+U+V (each 64x256B)
constexpr uint32_t SA    = STG0 + 2 * STAGE_BYTES;  // 131072; 128 rows x 128B
constexpr uint32_t SMEM_TOTAL = SA + 16384;         // 147456

} // namespace

// fp16 scratch (static device arrays: allowed scratch form)
__device__ __half g_Qh[(size_t)NB * NH * S * D];    // 8.4M elems
__device__ __half g_Kh[(size_t)HK * NI * D];        // 1M elems
__device__ __half g_Uh[(size_t)HK * NI * D];
__device__ __half g_Vh[(size_t)HK * NI * D];

// ======================= converters =======================

__global__ void conv_q(const float* __restrict__ s) {
    int i = blockIdx.x * 256 + threadIdx.x;           // one float4 per thread
    float4 v = reinterpret_cast<const float4*>(s)[i];
    __half2* d = reinterpret_cast<__half2*>(g_Qh);
    d[2 * i]     = __floats2half2_rn(v.x, v.y);
    d[2 * i + 1] = __floats2half2_rn(v.z, v.w);
}

__global__ void conv_kuv(const float* __restrict__ k, const float* __restrict__ u,
                         const float* __restrict__ v) {
    int i = blockIdx.x * 256 + threadIdx.x;
    const float* s;
    __half* dd;
    if (blockIdx.y == 0)      { s = k; dd = g_Kh; }
    else if (blockIdx.y == 1) { s = u; dd = g_Uh; }
    else                      { s = v; dd = g_Vh; }
    float4 val = reinterpret_cast<const float4*>(s)[i];
    __half2* d = reinterpret_cast<__half2*>(dd);
    d[2 * i]     = __floats2half2_rn(val.x, val.y);
    d[2 * i + 1] = __floats2half2_rn(val.z, val.w);
}

// ======================= PTX helpers =======================

DEVINL uint32_t smem_u32(const void* p) {
    uint32_t a;
    asm("{ .reg .u64 t; cvta.to.shared.u64 t, %1; cvt.u32.u64 %0, t; }" : "=r"(a) : "l"(p));
    return a;
}

DEVINL void cp16(uint32_t dst, const void* gsrc) {
    asm volatile("cp.async.cg.shared.global [%0], [%1], 16;"
                 :: "r"(dst), "l"(__cvta_generic_to_global(gsrc)) : "memory");
}
#define CP_COMMIT() asm volatile("cp.async.commit_group;" ::: "memory")
#define CP_WAIT1()  asm volatile("cp.async.wait_group 1;" ::: "memory")

DEVINL void ldsm_x4(uint32_t addr, uint32_t* r) {
    asm volatile("ldmatrix.sync.aligned.m8n8.x4.shared.b16 {%0,%1,%2,%3}, [%4];"
                 : "=r"(r[0]), "=r"(r[1]), "=r"(r[2]), "=r"(r[3]) : "r"(addr));
}
DEVINL void ldsm_x4_t(uint32_t addr, uint32_t* r) {
    asm volatile("ldmatrix.sync.aligned.m8n8.x4.trans.shared.b16 {%0,%1,%2,%3}, [%4];"
                 : "=r"(r[0]), "=r"(r[1]), "=r"(r[2]), "=r"(r[3]) : "r"(addr));
}
DEVINL void mma16816(float* d, const uint32_t* a, uint32_t b0, uint32_t b1) {
    asm volatile("mma.sync.aligned.m16n8k16.row.col.f32.f16.f16.f32 "
                 "{%0,%1,%2,%3},{%4,%5,%6,%7},{%8,%9},{%0,%1,%2,%3};"
                 : "+f"(d[0]), "+f"(d[1]), "+f"(d[2]), "+f"(d[3])
                 : "r"(a[0]), "r"(a[1]), "r"(a[2]), "r"(a[3]), "r"(b0), "r"(b1));
}
DEVINL void bar_pair(int id) {
    asm volatile("bar.sync %0, 64;" :: "r"(id) : "memory");
}

// silu-gate pair: a = silu(m*SCALE) * (n*SCALE)
DEVINL __half2 gate2(float m0, float m1, float n0, float n1) {
    m0 *= SCALE; m1 *= SCALE;
    float s0 = __fdividef(m0, 1.0f + __expf(-m0));
    float s1 = __fdividef(m1, 1.0f + __expf(-m1));
    return __floats2half2_rn(s0 * (n0 * SCALE), s1 * (n1 * SCALE));
}

// ======================= main kernel =======================

__global__ __launch_bounds__(THREADS, 1)
void flash_mlp_mma(float* __restrict__ gO) {
    extern __shared__ char smem[];
    const uint32_t sb = smem_u32(smem);

    const int tid  = threadIdx.x;
    const int wid  = tid >> 5;
    const int lane = tid & 31;
    const int wm   = wid >> 1;          // 0..3 : 32-row slice
    const int wn   = wid & 1;           // 0..1

    const int tileM = blockIdx.x;       // 0..15
    const int bh    = blockIdx.y;       // 0..31
    const int hk    = (bh & 15) >> 2;

    const __half* qG = g_Qh + ((size_t)bh * S + (size_t)tileM * BM) * D;
    const __half* kG = g_Kh + (size_t)hk * NI * D;
    const __half* uG = g_Uh + (size_t)hk * NI * D;
    const __half* vG = g_Vh + (size_t)hk * NI * D;
    float*        oB = gO   + ((size_t)bh * S + (size_t)tileM * BM) * D;

    // ---- cp.async Q (group with chunk 0) ----
    #pragma unroll
    for (int j = 0; j < 8; ++j) {
        int idx = tid + j * THREADS;        // 0..2047 16B chunks
        int r   = idx >> 4;
        int cc  = idx & 15;
        cp16(sb + SQ + r * 256 + ((cc * 16) ^ ((r & 7) << 4)), qG + r * D + cc * 8);
    }
    // ---- cp.async chunk loader ----
    auto load_chunk = [&](int c, int stg) {
        uint32_t base = sb + STG0 + (uint32_t)stg * STAGE_BYTES;
        #pragma unroll
        for (int j = 0; j < 4; ++j) {
            int idx = tid + j * THREADS;    // 0..1023
            int r   = idx >> 4;             // 0..63
            int cc  = idx & 15;
            uint32_t so = r * 256 + ((cc * 16) ^ ((r & 7) << 4));
            const size_t go = (size_t)(c * BI + r) * D + cc * 8;
            cp16(base + OFF_K + so, kG + go);
            cp16(base + OFF_U + so, uG + go);
            cp16(base + OFF_V + so, vG + go);
        }
    };

    load_chunk(0, 0); CP_COMMIT();
    load_chunk(1, 1); CP_COMMIT();

    float accO[2][8][4];
    #pragma unroll
    for (int a = 0; a < 2; ++a)
        #pragma unroll
        for (int b = 0; b < 8; ++b)
            #pragma unroll
            for (int c = 0; c < 4; ++c) accO[a][b][c] = 0.0f;

    for (int c = 0; c < NCHUNK; ++c) {
        CP_WAIT1();
        __syncthreads();
        const uint32_t stg = sb + STG0 + (uint32_t)(c & 1) * STAGE_BYTES;

        // ================= GEMM1/2: M = Q K^T, N = Q U^T =================
        float accM[2][4][4], accN[2][4][4];
        #pragma unroll
        for (int a = 0; a < 2; ++a)
            #pragma unroll
            for (int b = 0; b < 4; ++b)
                #pragma unroll
                for (int e = 0; e < 4; ++e) { accM[a][b][e] = 0.0f; accN[a][b][e] = 0.0f; }

        #pragma unroll
        for (int ks = 0; ks < 8; ++ks) {
            uint32_t afr[2][4];
            #pragma unroll
            for (int tm = 0; tm < 2; ++tm) {
                int r = wm * 32 + tm * 16 + (lane & 15);
                uint32_t byt = ks * 32 + ((lane >> 4) << 4);
                ldsm_x4(sb + SQ + r * 256 + (byt ^ ((r & 7) << 4)), afr[tm]);
            }
            #pragma unroll
            for (int p = 0; p < 2; ++p) {       // pairs of n-tiles
                uint32_t bk[4], bu[4];
                int g = lane >> 3;
                int nr = wn * 32 + p * 16 + ((g & 2) << 2) + (lane & 7);
                uint32_t byt = ks * 32 + ((g & 1) << 4);
                uint32_t so  = nr * 256 + (byt ^ ((nr & 7) << 4));
                ldsm_x4(stg + OFF_K + so, bk);
                ldsm_x4(stg + OFF_U + so, bu);
                #pragma unroll
                for (int tm = 0; tm < 2; ++tm) {
                    mma16816(accM[tm][2 * p + 0], afr[tm], bk[0], bk[1]);
                    mma16816(accM[tm][2 * p + 1], afr[tm], bk[2], bk[3]);
                    mma16816(accN[tm][2 * p + 0], afr[tm], bu[0], bu[1]);
                    mma16816(accN[tm][2 * p + 1], afr[tm], bu[2], bu[3]);
                }
            }
        }

        // ================= epilogue: A = silu(M*s) * (N*s) -> sA =================
        {
            const int g = lane >> 2, q = lane & 3;
            #pragma unroll
            for (int tm = 0; tm < 2; ++tm)
                #pragma unroll
                for (int tn = 0; tn < 4; ++tn) {
                    int r0 = wm * 32 + tm * 16 + g;
                    int r1 = r0 + 8;
                    uint32_t cb = wn * 64 + tn * 16 + q * 4;
                    __half2 h0 = gate2(accM[tm][tn][0], accM[tm][tn][1],
                                       accN[tm][tn][0], accN[tm][tn][1]);
                    __half2 h1 = gate2(accM[tm][tn][2], accM[tm][tn][3],
                                       accN[tm][tn][2], accN[tm][tn][3]);
                    *reinterpret_cast<__half2*>(smem + SA + r0 * 128 + (cb ^ ((r0 & 7) << 4))) = h0;
                    *reinterpret_cast<__half2*>(smem + SA + r1 * 128 + (cb ^ ((r1 & 7) << 4))) = h1;
                }
        }
        bar_pair(1 + wm);   // sA row-block wm ready (written by both wn warps)

        // ================= GEMM3: O += A V =================
        #pragma unroll
        for (int ks = 0; ks < 4; ++ks) {
            uint32_t afr[2][4];
            #pragma unroll
            for (int tm = 0; tm < 2; ++tm) {
                int r = wm * 32 + tm * 16 + (lane & 15);
                uint32_t byt = ks * 32 + ((lane >> 4) << 4);
                ldsm_x4(sb + SA + r * 128 + (byt ^ ((r & 7) << 4)), afr[tm]);
            }
            #pragma unroll
            for (int p = 0; p < 4; ++p) {       // pairs of n-tiles (16 cols)
                uint32_t bv[4];
                int g  = lane >> 3;
                int kr = ks * 16 + ((g & 1) << 3) + (lane & 7);
                uint32_t byt = (wn * 64 + p * 16) * 2 + ((g >> 1) << 4);
                ldsm_x4_t(stg + OFF_V + kr * 256 + (byt ^ ((kr & 7) << 4)), bv);
                #pragma unroll
                for (int tm = 0; tm < 2; ++tm) {
                    mma16816(accO[tm][2 * p + 0], afr[tm], bv[0], bv[1]);
                    mma16816(accO[tm][2 * p + 1], afr[tm], bv[2], bv[3]);
                }
            }
        }

        __syncthreads();   // everyone done with stage (c&1) and sA
        if (c + 2 < NCHUNK) load_chunk(c + 2, c & 1);
        CP_COMMIT();       // always commit (keeps wait_group accounting uniform)
    }

    // ================= write O =================
    {
        const int g = lane >> 2, q = lane & 3;
        #pragma unroll
        for (int tm = 0; tm < 2; ++tm)
            #pragma unroll
            for (int tn = 0; tn < 8; ++tn) {
                int r0  = wm * 32 + tm * 16 + g;
                int col = wn * 64 + tn * 8 + q * 2;
                float2 v0 = make_float2(accO[tm][tn][0], accO[tm][tn][1]);
                float2 v1 = make_float2(accO[tm][tn][2], accO[tm][tn][3]);
                *reinterpret_cast<float2*>(oB + (size_t)r0 * D + col)       = v0;
                *reinterpret_cast<float2*>(oB + (size_t)(r0 + 8) * D + col) = v1;
            }
    }
}

// ======================= launch =======================

extern "C" void kernel_launch(void* const* d_in, const int* in_sizes, int n_in,
                              void* d_out, int out_size) {
    const float* Q = (const float*)d_in[0];
    const float* K = (const float*)d_in[1];
    const float* U = (const float*)d_in[2];
    const float* V = (const float*)d_in[3];
    float* O = (float*)d_out;

    // converters
    conv_q<<<(NB * NH * S * D / 4) / 256, 256>>>(Q);               // 8192 blocks
    dim3 gk((HK * NI * D / 4) / 256, 3);                            // (512, 3)
    conv_kuv<<<gk, 256>>>(K, U, V);

    cudaFuncSetAttribute(flash_mlp_mma,
                         cudaFuncAttributeMaxDynamicSharedMemorySize, SMEM_TOTAL);
    dim3 grid(S / BM, NB * NH);   // (16, 32)
    flash_mlp_mma<<<grid, THREADS, SMEM_TOTAL>>>(O);
}